// round 1
// baseline (speedup 1.0000x reference)
#include <cuda_runtime.h>
#include <math.h>

// ---------------- problem constants ----------------
#define BB   16
#define WW   32
#define MM   512
#define NHID 64
#define NSEQ 8192   // B*M

// ---------------- scratch (device globals; no runtime alloc) ----------------
__device__ float g_hid[NSEQ * NHID];       // last_hid [n][64]
__device__ float g_e1[NSEQ * 32];
__device__ float g_e2[NSEQ * 32];
__device__ float g_amx[NSEQ * 512];        // a_mx [b*512+i][j]
__device__ float g_colsq[NSEQ];            // sum_i a^2 per (b,j)
__device__ float g_invn[NSEQ];
__device__ float g_adjmix[NSEQ * 512];     // gated mixed adjacency
__device__ float g_r[NSEQ * 24];           // relu(conv features)
__device__ float g_rg[NSEQ * 64];          // r @ gc1_w
__device__ float g_h1g[NSEQ * 10];         // h1 @ gc2_w

// ---------------- K0: zero column sumsq ----------------
__global__ void zero_colsq_kernel() {
    g_colsq[blockIdx.x * 256 + threadIdx.x] = 0.0f;
}

// ---------------- K1: RNN (+fused e1/e2 projections) ----------------
// block = 256 threads = 4 sequences x 64 hidden units.
// Whh row lives in registers; h broadcast via shared float4 reads.
__global__ void __launch_bounds__(256) rnn_kernel(
    const float* __restrict__ x, const float* __restrict__ Wih,
    const float* __restrict__ Whh, const float* __restrict__ bih,
    const float* __restrict__ bhh, const float* __restrict__ W1,
    const float* __restrict__ W2) {
    __shared__ __align__(16) float h_sh[2][4][64];
    __shared__ float seq_sh[4][32];
    int tid = threadIdx.x;
    int g = tid >> 6;        // sequence within block
    int j = tid & 63;        // hidden unit
    int n = blockIdx.x * 4 + g;

    float wr[64];
#pragma unroll
    for (int k = 0; k < 64; k++) wr[k] = Whh[j * 64 + k];
    float wih  = Wih[j];
    float bias = bih[j] + bhh[j];

    if (tid < 128) {
        int gg = tid >> 5, t = tid & 31;
        int nn = blockIdx.x * 4 + gg;
        seq_sh[gg][t] = x[((nn >> 9) * WW + t) * MM + (nn & 511)];
    }
    h_sh[1][g][j] = 0.0f;   // "prev" buffer for t=0
    __syncthreads();

    int cur = 0;
    float hval = 0.0f;
    for (int t = 0; t < 32; t++) {
        float acc = fmaf(seq_sh[g][t], wih, bias);
        const float4* hp = (const float4*)(h_sh[cur ^ 1][g]);
#pragma unroll
        for (int k4 = 0; k4 < 16; k4++) {
            float4 hv = hp[k4];
            acc = fmaf(hv.x, wr[4 * k4 + 0], acc);
            acc = fmaf(hv.y, wr[4 * k4 + 1], acc);
            acc = fmaf(hv.z, wr[4 * k4 + 2], acc);
            acc = fmaf(hv.w, wr[4 * k4 + 3], acc);
        }
        hval = tanhf(acc);
        h_sh[cur][g][j] = hval;
        __syncthreads();
        cur ^= 1;
    }
    g_hid[n * 64 + j] = hval;

    // fused e1/e2: threads 0..31 of the group -> e1, 32..63 -> e2
    const float* hrow = h_sh[cur ^ 1][g];   // final hidden state
    int hh = j & 31;
    const float* Wm = (j < 32) ? W1 : W2;
    float acc = 0.0f;
#pragma unroll
    for (int k = 0; k < 64; k++) acc = fmaf(hrow[k], Wm[hh * 64 + k], acc);
    if (j < 32) g_e1[n * 32 + hh] = acc;
    else        g_e2[n * 32 + hh] = acc;
}

// ---------------- K2: pairwise attention -> raw a_mx + column sumsq ----------------
__global__ void __launch_bounds__(256) attn_kernel(
    const float* __restrict__ b1, const float* __restrict__ V,
    const float* __restrict__ bv) {
    int b  = blockIdx.z;
    int i0 = blockIdx.y * 16, j0 = blockIdx.x * 16;
    __shared__ float e2s[16][33], e1s[16][33];
    __shared__ float b1s[32], Vs[32];
    __shared__ float part[16][17];
    int tx = threadIdx.x, ty = threadIdx.y;
    int tid = ty * 16 + tx;

    if (tid < 32) { b1s[tid] = b1[tid]; Vs[tid] = V[tid]; }
    {
        int r = tid >> 4;
        int c2 = (tid & 15) * 2;
        e2s[r][c2]     = g_e2[(b * 512 + i0 + r) * 32 + c2];
        e2s[r][c2 + 1] = g_e2[(b * 512 + i0 + r) * 32 + c2 + 1];
        e1s[r][c2]     = g_e1[(b * 512 + j0 + r) * 32 + c2];
        e1s[r][c2 + 1] = g_e1[(b * 512 + j0 + r) * 32 + c2 + 1];
    }
    __syncthreads();

    float acc = 0.0f;
#pragma unroll
    for (int h = 0; h < 32; h++) {
        float t = e2s[ty][h] + e1s[tx][h] + b1s[h];
        float v = (t > 0.0f) ? t : (__expf(t) - 1.0f);   // elu
        acc = fmaf(v, Vs[h], acc);
    }
    float out = acc + bv[0];
    int i = i0 + ty, j = j0 + tx;
    g_amx[(b * 512 + i) * 512 + j] = out;
    part[ty][tx] = out * out;
    __syncthreads();
    if (ty == 0) {
        float s = 0.0f;
#pragma unroll
        for (int r = 0; r < 16; r++) s += part[r][tx];
        atomicAdd(&g_colsq[b * 512 + j], s);
    }
}

// ---------------- K3: inverse column norms; K4: scale a_mx in place ----------------
__global__ void invnorm_kernel() {
    int i = blockIdx.x * 256 + threadIdx.x;
    g_invn[i] = 1.0f / fmaxf(sqrtf(g_colsq[i]), 1e-12f);
}
__global__ void scale_amx_kernel() {
    int t = blockIdx.x * 256 + threadIdx.x;   // over 8192*512
    int n = t >> 9;
    int b = n >> 9;
    int j = t & 511;
    g_amx[t] *= g_invn[b * 512 + j];
}

// ---------------- K5: C = a_mx @ Wb, fused sigmoid gate -> adj_mix ----------------
// 128x128 tile, KT=8, 256 threads, 8x8 microtile, double-buffered smem.
__global__ void __launch_bounds__(256) gemm_c_kernel(
    const float* __restrict__ Wb, const float* __restrict__ wb,
    const float* __restrict__ adj) {
    __shared__ __align__(16) float As[2][8][128];
    __shared__ __align__(16) float Bs[2][8][128];
    int tid = threadIdx.x;
    int n0 = blockIdx.y * 128, j0 = blockIdx.x * 128;
    int tx = tid & 15, ty = tid >> 4;
    float acc[8][8];
#pragma unroll
    for (int u = 0; u < 8; u++)
#pragma unroll
        for (int v = 0; v < 8; v++) acc[u][v] = 0.0f;

    int arow = tid >> 1, ac4 = (tid & 1) * 4;
    int brow = tid >> 5, bc4 = (tid & 31) * 4;
    const float* Aptr = &g_amx[(n0 + arow) * 512 + ac4];
    const float* Bptr = &Wb[brow * 512 + j0 + bc4];

    float4 av = *(const float4*)Aptr;
    float4 bv = *(const float4*)Bptr;
    As[0][ac4 + 0][arow] = av.x; As[0][ac4 + 1][arow] = av.y;
    As[0][ac4 + 2][arow] = av.z; As[0][ac4 + 3][arow] = av.w;
    *(float4*)&Bs[0][brow][bc4] = bv;
    __syncthreads();

    for (int kt = 0; kt < 64; kt++) {
        int cur = kt & 1;
        if (kt < 63) {
            av = *(const float4*)(Aptr + (kt + 1) * 8);
            bv = *(const float4*)(Bptr + (kt + 1) * 8 * 512);
        }
#pragma unroll
        for (int k = 0; k < 8; k++) {
            float4 a0 = *(const float4*)&As[cur][k][ty * 4];
            float4 a1 = *(const float4*)&As[cur][k][64 + ty * 4];
            float4 b0 = *(const float4*)&Bs[cur][k][tx * 4];
            float4 b1 = *(const float4*)&Bs[cur][k][64 + tx * 4];
            float a_[8] = {a0.x, a0.y, a0.z, a0.w, a1.x, a1.y, a1.z, a1.w};
            float b_[8] = {b0.x, b0.y, b0.z, b0.w, b1.x, b1.y, b1.z, b1.w};
#pragma unroll
            for (int u = 0; u < 8; u++)
#pragma unroll
                for (int v = 0; v < 8; v++)
                    acc[u][v] = fmaf(a_[u], b_[v], acc[u][v]);
        }
        if (kt < 63) {
            int nb = cur ^ 1;
            As[nb][ac4 + 0][arow] = av.x; As[nb][ac4 + 1][arow] = av.y;
            As[nb][ac4 + 2][arow] = av.z; As[nb][ac4 + 3][arow] = av.w;
            *(float4*)&Bs[nb][brow][bc4] = bv;
        }
        __syncthreads();
    }

    float wbv = wb[0];
#pragma unroll
    for (int u = 0; u < 8; u++) {
        int rr = (u < 4) ? (ty * 4 + u) : (64 + ty * 4 + u - 4);
        int n = n0 + rr;
        int irow = n & 511;
#pragma unroll
        for (int v = 0; v < 8; v++) {
            int cc = (v < 4) ? (tx * 4 + v) : (64 + tx * 4 + v - 4);
            int jj = j0 + cc;
            float s = 1.0f / (1.0f + __expf(-(acc[u][v] + wbv)));
            float am = g_amx[n * 512 + jj];   // already normalized
            g_adjmix[n * 512 + jj] = fmaf(adj[irow * 512 + jj], s, am * (1.0f - s));
        }
    }
}

// ---------------- K6: conv features r (relu) ----------------
__global__ void __launch_bounds__(256) conv_kernel(
    const float* __restrict__ x, const float* __restrict__ conv_w,
    const float* __restrict__ conv_b, const float* __restrict__ convl_w,
    const float* __restrict__ convl_b) {
    __shared__ float cw[256], clw[128], cb[8], clb[8];
    int tid = threadIdx.x;
    cw[tid] = conv_w[tid];
    if (tid < 128) clw[tid] = convl_w[tid];
    if (tid < 8) { cb[tid] = conv_b[tid]; clb[tid] = convl_b[tid]; }
    __syncthreads();

    int n = blockIdx.x * 256 + tid;
    int b = n >> 9, m = n & 511;
    float s[32];
#pragma unroll
    for (int t = 0; t < 32; t++) s[t] = x[(b * 32 + t) * 512 + m];
#pragma unroll
    for (int k = 0; k < 8; k++) {
        float a0 = cb[k], a1 = clb[k], a2 = clb[k];
#pragma unroll
        for (int t = 0; t < 32; t++) a0 = fmaf(s[t], cw[k * 32 + t], a0);
#pragma unroll
        for (int i = 0; i < 16; i++) {           // dilation 2, out len 2
            a1 = fmaf(s[2 * i],     clw[k * 16 + i], a1);
            a2 = fmaf(s[2 * i + 1], clw[k * 16 + i], a2);
        }
        g_r[n * 24 + k * 3 + 0] = fmaxf(a0, 0.0f);
        g_r[n * 24 + k * 3 + 1] = fmaxf(a1, 0.0f);
        g_r[n * 24 + k * 3 + 2] = fmaxf(a2, 0.0f);
    }
}

// ---------------- K7: rg = r @ gc1_w ----------------
__global__ void __launch_bounds__(256) rg_kernel(const float* __restrict__ gc1_w) {
    int t = blockIdx.x * 256 + threadIdx.x;   // over 8192*64
    int n = t >> 6, j = t & 63;
    float acc = 0.0f;
#pragma unroll
    for (int idx = 0; idx < 24; idx++)
        acc = fmaf(g_r[n * 24 + idx], gc1_w[idx * 64 + j], acc);
    g_rg[t] = acc;
}

// ---------------- K8: h1 = relu(adj_mix @ rg + gc1_b); fused h1g = h1 @ gc2_w ----------------
__global__ void __launch_bounds__(256) h1_kernel(
    const float* __restrict__ gc1_b, const float* __restrict__ gc2_w) {
    __shared__ __align__(16) float As[16][68];
    __shared__ __align__(16) float Bs[16][68];
    __shared__ float h1s[64][65];
    __shared__ float g2s[640];
    int tid = threadIdx.x;
    int bb = blockIdx.y;
    int i0 = blockIdx.x * 64;
    int tx = tid & 15, ty = tid >> 4;
    float acc[4][4];
#pragma unroll
    for (int u = 0; u < 4; u++)
#pragma unroll
        for (int v = 0; v < 4; v++) acc[u][v] = 0.0f;
    for (int t = tid; t < 640; t += 256) g2s[t] = gc2_w[t];

    int arow = tid >> 2, ac4 = (tid & 3) * 4;
    int brow = tid >> 4, bc4 = (tid & 15) * 4;
    for (int kt = 0; kt < 32; kt++) {
        int k0 = kt * 16;
        float4 av  = *(const float4*)&g_adjmix[(bb * 512 + i0 + arow) * 512 + k0 + ac4];
        float4 bvv = *(const float4*)&g_rg[(bb * 512 + k0 + brow) * 64 + bc4];
        __syncthreads();
        As[ac4 + 0][arow] = av.x; As[ac4 + 1][arow] = av.y;
        As[ac4 + 2][arow] = av.z; As[ac4 + 3][arow] = av.w;
        *(float4*)&Bs[brow][bc4] = bvv;
        __syncthreads();
#pragma unroll
        for (int k = 0; k < 16; k++) {
            float4 a = *(const float4*)&As[k][ty * 4];
            float4 b = *(const float4*)&Bs[k][tx * 4];
            float a_[4] = {a.x, a.y, a.z, a.w};
            float b_[4] = {b.x, b.y, b.z, b.w};
#pragma unroll
            for (int u = 0; u < 4; u++)
#pragma unroll
                for (int v = 0; v < 4; v++)
                    acc[u][v] = fmaf(a_[u], b_[v], acc[u][v]);
        }
    }
    __syncthreads();
#pragma unroll
    for (int u = 0; u < 4; u++)
#pragma unroll
        for (int v = 0; v < 4; v++)
            h1s[ty * 4 + u][tx * 4 + v] = fmaxf(acc[u][v] + gc1_b[tx * 4 + v], 0.0f);
    __syncthreads();
    for (int idx = tid; idx < 640; idx += 256) {
        int i = idx & 63, jj = idx >> 6;
        float a = 0.0f;
#pragma unroll
        for (int j = 0; j < 64; j++) a = fmaf(h1s[i][j], g2s[j * 10 + jj], a);
        g_h1g[(bb * 512 + i0 + i) * 10 + jj] = a;
    }
}

// ---------------- K9: out_spatial = relu(adj_mix @ h1g + gc2_b); fused output head ----------------
__global__ void __launch_bounds__(640) out_kernel(
    const float* __restrict__ gc2_b, const float* __restrict__ out_w,
    const float* __restrict__ out_b, float* __restrict__ out) {
    __shared__ float adjs[64][65];
    __shared__ float hgs[64][12];
    __shared__ float oss[64][13];
    __shared__ float hids[64][65];
    __shared__ float ows[592];
    __shared__ float gbs[10], obs[8];
    int tid = threadIdx.x;
    int bb = blockIdx.y;
    int i0 = blockIdx.x * 64;
    for (int t = tid; t < 592; t += 640) ows[t] = out_w[t];
    if (tid < 10) gbs[tid] = gc2_b[tid];
    if (tid < 8)  obs[tid] = out_b[tid];

    int il = tid / 10;   // 0..63
    int jj = tid % 10;
    float acc = 0.0f;
    for (int kt = 0; kt < 8; kt++) {
        __syncthreads();
        for (int idx = tid; idx < 4096; idx += 640) {
            int r = idx >> 6, c = idx & 63;
            adjs[r][c] = g_adjmix[(bb * 512 + i0 + r) * 512 + kt * 64 + c];
        }
        {
            int kr = tid / 10, j2 = tid % 10;
            hgs[kr][j2] = g_h1g[(bb * 512 + kt * 64 + kr) * 10 + j2];
        }
        __syncthreads();
#pragma unroll 8
        for (int k = 0; k < 64; k++) acc = fmaf(adjs[il][k], hgs[k][jj], acc);
    }
    __syncthreads();
    oss[il][jj] = fmaxf(acc + gbs[jj], 0.0f);
    for (int idx = tid; idx < 4096; idx += 640) {
        int r = idx >> 6, c = idx & 63;
        hids[r][c] = g_hid[(bb * 512 + i0 + r) * 64 + c];
    }
    __syncthreads();
    if (tid < 512) {
        int h = tid >> 6, i = tid & 63;
        float a = obs[h];
#pragma unroll
        for (int q = 0; q < 10; q++) a = fmaf(oss[i][q], ows[h * 74 + q], a);
#pragma unroll
        for (int t = 0; t < 64; t++) a = fmaf(hids[i][t], ows[h * 74 + 10 + t], a);
        out[bb * 4096 + h * 512 + i0 + i] = a;
    }
}

// ---------------- launch ----------------
extern "C" void kernel_launch(void* const* d_in, const int* in_sizes, int n_in,
                              void* d_out, int out_size) {
    const float* x       = (const float*)d_in[0];
    const float* adj     = (const float*)d_in[1];
    const float* Wih     = (const float*)d_in[2];
    const float* Whh     = (const float*)d_in[3];
    const float* bih     = (const float*)d_in[4];
    const float* bhh     = (const float*)d_in[5];
    const float* W1      = (const float*)d_in[6];
    const float* W2      = (const float*)d_in[7];
    const float* b1      = (const float*)d_in[8];
    const float* V       = (const float*)d_in[9];
    const float* bv      = (const float*)d_in[10];
    const float* Wb      = (const float*)d_in[11];
    const float* wb      = (const float*)d_in[12];
    const float* conv_w  = (const float*)d_in[13];
    const float* conv_b  = (const float*)d_in[14];
    const float* convl_w = (const float*)d_in[15];
    const float* convl_b = (const float*)d_in[16];
    const float* gc1_w   = (const float*)d_in[17];
    const float* gc1_b   = (const float*)d_in[18];
    const float* gc2_w   = (const float*)d_in[19];
    const float* gc2_b   = (const float*)d_in[20];
    const float* out_w   = (const float*)d_in[21];
    const float* out_b   = (const float*)d_in[22];
    float* out = (float*)d_out;

    zero_colsq_kernel<<<32, 256>>>();
    rnn_kernel<<<2048, 256>>>(x, Wih, Whh, bih, bhh, W1, W2);
    conv_kernel<<<32, 256>>>(x, conv_w, conv_b, convl_w, convl_b);
    rg_kernel<<<2048, 256>>>(gc1_w);
    attn_kernel<<<dim3(32, 32, 16), dim3(16, 16)>>>(b1, V, bv);
    invnorm_kernel<<<32, 256>>>();
    scale_amx_kernel<<<16384, 256>>>();
    gemm_c_kernel<<<dim3(4, 64), 256>>>(Wb, wb, adj);
    h1_kernel<<<dim3(8, 16), 256>>>(gc1_b, gc2_w);
    out_kernel<<<dim3(8, 16), 640>>>(gc2_b, out_w, out_b, out);
}

// round 2
// speedup vs baseline: 1.0341x; 1.0341x over previous
#include <cuda_runtime.h>
#include <math.h>

// ---------------- problem constants ----------------
#define BB   16
#define WW   32
#define MM   512
#define NHID 64
#define NSEQ 8192   // B*M

// ---------------- scratch (device globals; no runtime alloc) ----------------
__device__ float g_hid[NSEQ * NHID];       // last_hid [n][64]
__device__ float g_e1[NSEQ * 32];
__device__ float g_e2[NSEQ * 32];
__device__ float g_amx[NSEQ * 512];        // RAW a_mx (pre-normalization)
__device__ float g_colsq[NSEQ];            // sum_i a^2 per (b,j)
__device__ float g_invn[NSEQ];
__device__ float g_adjmix[NSEQ * 512];     // gated mixed adjacency
__device__ float g_rg[NSEQ * 64];          // relu(conv feats) @ gc1_w
__device__ float g_h1g[NSEQ * 10];         // h1 @ gc2_w

// fast accurate tanh: (e^2x - 1)/(e^2x + 1), MUFU ex2 + rcp
__device__ __forceinline__ float fast_tanh(float x) {
    x = fminf(fmaxf(x, -10.0f), 10.0f);
    float e = __expf(2.0f * x);
    return __fdividef(e - 1.0f, e + 1.0f);
}

// ---------------- K0: zero column sumsq ----------------
__global__ void zero_colsq_kernel() {
    g_colsq[blockIdx.x * 256 + threadIdx.x] = 0.0f;
}

// ---------------- K1: RNN (+fused e1/e2 projections) ----------------
__global__ void __launch_bounds__(256) rnn_kernel(
    const float* __restrict__ x, const float* __restrict__ Wih,
    const float* __restrict__ Whh, const float* __restrict__ bih,
    const float* __restrict__ bhh, const float* __restrict__ W1,
    const float* __restrict__ W2) {
    __shared__ __align__(16) float h_sh[2][4][64];
    __shared__ float seq_sh[4][32];
    int tid = threadIdx.x;
    int g = tid >> 6;        // sequence within block
    int j = tid & 63;        // hidden unit
    int n = blockIdx.x * 4 + g;

    float wr[64];
#pragma unroll
    for (int k = 0; k < 64; k++) wr[k] = Whh[j * 64 + k];
    float wih  = Wih[j];
    float bias = bih[j] + bhh[j];

    if (tid < 128) {
        int gg = tid >> 5, t = tid & 31;
        int nn = blockIdx.x * 4 + gg;
        seq_sh[gg][t] = x[((nn >> 9) * WW + t) * MM + (nn & 511)];
    }
    h_sh[1][g][j] = 0.0f;   // "prev" buffer for t=0
    __syncthreads();

    int cur = 0;
    float hval = 0.0f;
    for (int t = 0; t < 32; t++) {
        float a0 = fmaf(seq_sh[g][t], wih, bias);
        float a1 = 0.0f, a2 = 0.0f, a3 = 0.0f;
        const float4* hp = (const float4*)(h_sh[cur ^ 1][g]);
#pragma unroll
        for (int k4 = 0; k4 < 4; k4++) {
#pragma unroll
            for (int q = 0; q < 4; q++) {
                float4 hv = hp[k4 * 4 + q];
                int base = (k4 * 4 + q) * 4;
                float* accp = (q == 0) ? &a0 : (q == 1) ? &a1 : (q == 2) ? &a2 : &a3;
                *accp = fmaf(hv.x, wr[base + 0], *accp);
                *accp = fmaf(hv.y, wr[base + 1], *accp);
                *accp = fmaf(hv.z, wr[base + 2], *accp);
                *accp = fmaf(hv.w, wr[base + 3], *accp);
            }
        }
        hval = fast_tanh((a0 + a1) + (a2 + a3));
        h_sh[cur][g][j] = hval;
        __syncthreads();
        cur ^= 1;
    }
    g_hid[n * 64 + j] = hval;

    // fused e1/e2: threads 0..31 of the group -> e1, 32..63 -> e2
    const float* hrow = h_sh[cur ^ 1][g];
    int hh = j & 31;
    const float* Wm = (j < 32) ? W1 : W2;
    float acc = 0.0f;
#pragma unroll
    for (int k = 0; k < 64; k++) acc = fmaf(hrow[k], Wm[hh * 64 + k], acc);
    if (j < 32) g_e1[n * 32 + hh] = acc;
    else        g_e2[n * 32 + hh] = acc;
}

// ---------------- K2: pairwise attention -> raw a_mx + column sumsq ----------------
__global__ void __launch_bounds__(256) attn_kernel(
    const float* __restrict__ b1, const float* __restrict__ V,
    const float* __restrict__ bv) {
    int b  = blockIdx.z;
    int i0 = blockIdx.y * 16, j0 = blockIdx.x * 16;
    __shared__ float e2s[16][33], e1s[16][33];
    __shared__ float Vs[32];
    __shared__ float part[16][17];
    int tx = threadIdx.x, ty = threadIdx.y;
    int tid = ty * 16 + tx;

    if (tid < 32) Vs[tid] = V[tid];
    {
        int r = tid >> 4;
        int c2 = (tid & 15) * 2;
        // pre-fold b1 into e2 tile (i role)
        e2s[r][c2]     = g_e2[(b * 512 + i0 + r) * 32 + c2]     + b1[c2];
        e2s[r][c2 + 1] = g_e2[(b * 512 + i0 + r) * 32 + c2 + 1] + b1[c2 + 1];
        e1s[r][c2]     = g_e1[(b * 512 + j0 + r) * 32 + c2];
        e1s[r][c2 + 1] = g_e1[(b * 512 + j0 + r) * 32 + c2 + 1];
    }
    __syncthreads();

    float acc = 0.0f;
#pragma unroll
    for (int h = 0; h < 32; h++) {
        float t = e2s[ty][h] + e1s[tx][h];
        float v = (t > 0.0f) ? t : (__expf(t) - 1.0f);   // elu
        acc = fmaf(v, Vs[h], acc);
    }
    float out = acc + bv[0];
    int i = i0 + ty, j = j0 + tx;
    g_amx[(b * 512 + i) * 512 + j] = out;
    part[ty][tx] = out * out;
    __syncthreads();
    if (ty == 0) {
        float s = 0.0f;
#pragma unroll
        for (int r = 0; r < 16; r++) s += part[r][tx];
        atomicAdd(&g_colsq[b * 512 + j], s);
    }
}

// ---------------- K3: inverse column norms ----------------
__global__ void invnorm_kernel() {
    int i = blockIdx.x * 256 + threadIdx.x;
    g_invn[i] = 1.0f / fmaxf(sqrtf(g_colsq[i]), 1e-12f);
}

// ---------------- K5: C = norm(a_mx) @ Wb, fused sigmoid gate -> adj_mix ----------------
// Normalization folded in: A smem tiles and the epilogue read of a_mx are both
// scaled by inv_sh[] (per-(b,j) inverse column norm).
__global__ void __launch_bounds__(256) gemm_c_kernel(
    const float* __restrict__ Wb, const float* __restrict__ wb,
    const float* __restrict__ adj) {
    __shared__ __align__(16) float As[2][8][128];
    __shared__ __align__(16) float Bs[2][8][128];
    __shared__ __align__(16) float inv_sh[512];
    int tid = threadIdx.x;
    int n0 = blockIdx.y * 128, j0 = blockIdx.x * 128;
    int b  = n0 >> 9;
    int tx = tid & 15, ty = tid >> 4;
    float acc[8][8];
#pragma unroll
    for (int u = 0; u < 8; u++)
#pragma unroll
        for (int v = 0; v < 8; v++) acc[u][v] = 0.0f;

    inv_sh[tid]       = g_invn[b * 512 + tid];
    inv_sh[tid + 256] = g_invn[b * 512 + tid + 256];

    int arow = tid >> 1, ac4 = (tid & 1) * 4;
    int brow = tid >> 5, bc4 = (tid & 31) * 4;
    const float* Aptr = &g_amx[(n0 + arow) * 512 + ac4];
    const float* Bptr = &Wb[brow * 512 + j0 + bc4];

    float4 av = *(const float4*)Aptr;
    float4 bv = *(const float4*)Bptr;
    __syncthreads();   // inv_sh ready
    {
        float4 iv = *(const float4*)&inv_sh[ac4];
        As[0][ac4 + 0][arow] = av.x * iv.x; As[0][ac4 + 1][arow] = av.y * iv.y;
        As[0][ac4 + 2][arow] = av.z * iv.z; As[0][ac4 + 3][arow] = av.w * iv.w;
    }
    *(float4*)&Bs[0][brow][bc4] = bv;
    __syncthreads();

    for (int kt = 0; kt < 64; kt++) {
        int cur = kt & 1;
        if (kt < 63) {
            av = *(const float4*)(Aptr + (kt + 1) * 8);
            bv = *(const float4*)(Bptr + (kt + 1) * 8 * 512);
        }
#pragma unroll
        for (int k = 0; k < 8; k++) {
            float4 a0 = *(const float4*)&As[cur][k][ty * 4];
            float4 a1 = *(const float4*)&As[cur][k][64 + ty * 4];
            float4 b0 = *(const float4*)&Bs[cur][k][tx * 4];
            float4 b1 = *(const float4*)&Bs[cur][k][64 + tx * 4];
            float a_[8] = {a0.x, a0.y, a0.z, a0.w, a1.x, a1.y, a1.z, a1.w};
            float b_[8] = {b0.x, b0.y, b0.z, b0.w, b1.x, b1.y, b1.z, b1.w};
#pragma unroll
            for (int u = 0; u < 8; u++)
#pragma unroll
                for (int v = 0; v < 8; v++)
                    acc[u][v] = fmaf(a_[u], b_[v], acc[u][v]);
        }
        if (kt < 63) {
            int nb = cur ^ 1;
            float4 iv = *(const float4*)&inv_sh[(kt + 1) * 8 + ac4];
            As[nb][ac4 + 0][arow] = av.x * iv.x; As[nb][ac4 + 1][arow] = av.y * iv.y;
            As[nb][ac4 + 2][arow] = av.z * iv.z; As[nb][ac4 + 3][arow] = av.w * iv.w;
            *(float4*)&Bs[nb][brow][bc4] = bv;
        }
        __syncthreads();
    }

    float wbv = wb[0];
#pragma unroll
    for (int u = 0; u < 8; u++) {
        int rr = (u < 4) ? (ty * 4 + u) : (64 + ty * 4 + u - 4);
        int n = n0 + rr;
        int irow = n & 511;
#pragma unroll
        for (int v = 0; v < 8; v++) {
            int cc = (v < 4) ? (tx * 4 + v) : (64 + tx * 4 + v - 4);
            int jj = j0 + cc;
            float s = 1.0f / (1.0f + __expf(-(acc[u][v] + wbv)));
            float am = g_amx[n * 512 + jj] * inv_sh[jj];   // normalize on read
            g_adjmix[n * 512 + jj] = fmaf(adj[irow * 512 + jj], s, am * (1.0f - s));
        }
    }
}

// ---------------- K6: fused conv features + rg = relu(r) @ gc1_w ----------------
// block = 256 threads = 4 sequences x 64 output cols; r kept in smem.
__global__ void __launch_bounds__(256) convrg_kernel(
    const float* __restrict__ x, const float* __restrict__ conv_w,
    const float* __restrict__ conv_b, const float* __restrict__ convl_w,
    const float* __restrict__ convl_b, const float* __restrict__ gc1_w) {
    __shared__ float cw[256], clw[128], cb[8], clb[8];
    __shared__ float seq[4][32];
    __shared__ float r_sh[4][24];
    __shared__ float g1s[24 * 64];
    int tid = threadIdx.x;
    cw[tid] = conv_w[tid];
    if (tid < 128) clw[tid] = convl_w[tid];
    if (tid < 8) { cb[tid] = conv_b[tid]; clb[tid] = convl_b[tid]; }
    for (int t = tid; t < 24 * 64; t += 256) g1s[t] = gc1_w[t];
    if (tid < 128) {
        int gg = tid >> 5, t = tid & 31;
        int nn = blockIdx.x * 4 + gg;
        seq[gg][t] = x[((nn >> 9) * WW + t) * MM + (nn & 511)];
    }
    __syncthreads();

    if (tid < 96) {
        int g = tid / 24, idx = tid % 24;
        int k = idx / 3, c = idx % 3;
        float a;
        if (c == 0) {
            a = cb[k];
#pragma unroll
            for (int t = 0; t < 32; t++) a = fmaf(seq[g][t], cw[k * 32 + t], a);
        } else {
            a = clb[k];
#pragma unroll
            for (int i = 0; i < 16; i++)
                a = fmaf(seq[g][2 * i + (c - 1)], clw[k * 16 + i], a);
        }
        r_sh[g][idx] = fmaxf(a, 0.0f);
    }
    __syncthreads();

    int g = tid >> 6, j = tid & 63;
    int n = blockIdx.x * 4 + g;
    float acc = 0.0f;
#pragma unroll
    for (int idx = 0; idx < 24; idx++)
        acc = fmaf(r_sh[g][idx], g1s[idx * 64 + j], acc);
    g_rg[n * 64 + j] = acc;
}

// ---------------- K8: h1 = relu(adj_mix @ rg + gc1_b); fused h1g = h1 @ gc2_w ----------------
__global__ void __launch_bounds__(256) h1_kernel(
    const float* __restrict__ gc1_b, const float* __restrict__ gc2_w) {
    __shared__ __align__(16) float As[16][68];
    __shared__ __align__(16) float Bs[16][68];
    __shared__ float h1s[64][65];
    __shared__ float g2s[640];
    int tid = threadIdx.x;
    int bb = blockIdx.y;
    int i0 = blockIdx.x * 64;
    int tx = tid & 15, ty = tid >> 4;
    float acc[4][4];
#pragma unroll
    for (int u = 0; u < 4; u++)
#pragma unroll
        for (int v = 0; v < 4; v++) acc[u][v] = 0.0f;
    for (int t = tid; t < 640; t += 256) g2s[t] = gc2_w[t];

    int arow = tid >> 2, ac4 = (tid & 3) * 4;
    int brow = tid >> 4, bc4 = (tid & 15) * 4;
    // prefetch tile 0
    float4 av  = *(const float4*)&g_adjmix[(bb * 512 + i0 + arow) * 512 + ac4];
    float4 bvv = *(const float4*)&g_rg[(bb * 512 + brow) * 64 + bc4];
    for (int kt = 0; kt < 32; kt++) {
        __syncthreads();
        As[ac4 + 0][arow] = av.x; As[ac4 + 1][arow] = av.y;
        As[ac4 + 2][arow] = av.z; As[ac4 + 3][arow] = av.w;
        *(float4*)&Bs[brow][bc4] = bvv;
        __syncthreads();
        if (kt < 31) {
            int k0 = (kt + 1) * 16;
            av  = *(const float4*)&g_adjmix[(bb * 512 + i0 + arow) * 512 + k0 + ac4];
            bvv = *(const float4*)&g_rg[(bb * 512 + k0 + brow) * 64 + bc4];
        }
#pragma unroll
        for (int k = 0; k < 16; k++) {
            float4 a = *(const float4*)&As[k][ty * 4];
            float4 b = *(const float4*)&Bs[k][tx * 4];
            float a_[4] = {a.x, a.y, a.z, a.w};
            float b_[4] = {b.x, b.y, b.z, b.w};
#pragma unroll
            for (int u = 0; u < 4; u++)
#pragma unroll
                for (int v = 0; v < 4; v++)
                    acc[u][v] = fmaf(a_[u], b_[v], acc[u][v]);
        }
    }
    __syncthreads();
#pragma unroll
    for (int u = 0; u < 4; u++)
#pragma unroll
        for (int v = 0; v < 4; v++)
            h1s[ty * 4 + u][tx * 4 + v] = fmaxf(acc[u][v] + gc1_b[tx * 4 + v], 0.0f);
    __syncthreads();
    for (int idx = tid; idx < 640; idx += 256) {
        int i = idx & 63, jj = idx >> 6;
        float a = 0.0f;
#pragma unroll
        for (int j = 0; j < 64; j++) a = fmaf(h1s[i][j], g2s[j * 10 + jj], a);
        g_h1g[(bb * 512 + i0 + i) * 10 + jj] = a;
    }
}

// ---------------- K9: out_spatial = relu(adj_mix @ h1g + gc2_b); fused output head ----------------
__global__ void __launch_bounds__(640) out_kernel(
    const float* __restrict__ gc2_b, const float* __restrict__ out_w,
    const float* __restrict__ out_b, float* __restrict__ out) {
    __shared__ float adjs[64][65];
    __shared__ float hgs[64][12];
    __shared__ float oss[64][13];
    __shared__ float hids[64][65];
    __shared__ float ows[592];
    __shared__ float gbs[10], obs[8];
    int tid = threadIdx.x;
    int bb = blockIdx.y;
    int i0 = blockIdx.x * 64;
    for (int t = tid; t < 592; t += 640) ows[t] = out_w[t];
    if (tid < 10) gbs[tid] = gc2_b[tid];
    if (tid < 8)  obs[tid] = out_b[tid];

    int il = tid / 10;   // 0..63
    int jj = tid % 10;
    float acc = 0.0f;
    for (int kt = 0; kt < 8; kt++) {
        __syncthreads();
        for (int idx = tid; idx < 4096; idx += 640) {
            int r = idx >> 6, c = idx & 63;
            adjs[r][c] = g_adjmix[(bb * 512 + i0 + r) * 512 + kt * 64 + c];
        }
        {
            int kr = tid / 10, j2 = tid % 10;
            hgs[kr][j2] = g_h1g[(bb * 512 + kt * 64 + kr) * 10 + j2];
        }
        __syncthreads();
#pragma unroll 8
        for (int k = 0; k < 64; k++) acc = fmaf(adjs[il][k], hgs[k][jj], acc);
    }
    __syncthreads();
    oss[il][jj] = fmaxf(acc + gbs[jj], 0.0f);
    for (int idx = tid; idx < 4096; idx += 640) {
        int r = idx >> 6, c = idx & 63;
        hids[r][c] = g_hid[(bb * 512 + i0 + r) * 64 + c];
    }
    __syncthreads();
    if (tid < 512) {
        int h = tid >> 6, i = tid & 63;
        float a = obs[h];
#pragma unroll
        for (int q = 0; q < 10; q++) a = fmaf(oss[i][q], ows[h * 74 + q], a);
#pragma unroll
        for (int t = 0; t < 64; t++) a = fmaf(hids[i][t], ows[h * 74 + 10 + t], a);
        out[bb * 4096 + h * 512 + i0 + i] = a;
    }
}

// ---------------- launch ----------------
extern "C" void kernel_launch(void* const* d_in, const int* in_sizes, int n_in,
                              void* d_out, int out_size) {
    const float* x       = (const float*)d_in[0];
    const float* adj     = (const float*)d_in[1];
    const float* Wih     = (const float*)d_in[2];
    const float* Whh     = (const float*)d_in[3];
    const float* bih     = (const float*)d_in[4];
    const float* bhh     = (const float*)d_in[5];
    const float* W1      = (const float*)d_in[6];
    const float* W2      = (const float*)d_in[7];
    const float* b1      = (const float*)d_in[8];
    const float* V       = (const float*)d_in[9];
    const float* bv      = (const float*)d_in[10];
    const float* Wb      = (const float*)d_in[11];
    const float* wb      = (const float*)d_in[12];
    const float* conv_w  = (const float*)d_in[13];
    const float* conv_b  = (const float*)d_in[14];
    const float* convl_w = (const float*)d_in[15];
    const float* convl_b = (const float*)d_in[16];
    const float* gc1_w   = (const float*)d_in[17];
    const float* gc1_b   = (const float*)d_in[18];
    const float* gc2_w   = (const float*)d_in[19];
    const float* gc2_b   = (const float*)d_in[20];
    const float* out_w   = (const float*)d_in[21];
    const float* out_b   = (const float*)d_in[22];
    float* out = (float*)d_out;

    zero_colsq_kernel<<<32, 256>>>();
    rnn_kernel<<<2048, 256>>>(x, Wih, Whh, bih, bhh, W1, W2);
    convrg_kernel<<<2048, 256>>>(x, conv_w, conv_b, convl_w, convl_b, gc1_w);
    attn_kernel<<<dim3(32, 32, 16), dim3(16, 16)>>>(b1, V, bv);
    invnorm_kernel<<<32, 256>>>();
    gemm_c_kernel<<<dim3(4, 64), 256>>>(Wb, wb, adj);
    h1_kernel<<<dim3(8, 16), 256>>>(gc1_b, gc2_w);
    out_kernel<<<dim3(8, 16), 640>>>(gc2_b, out_w, out_b, out);
}